// round 2
// baseline (speedup 1.0000x reference)
#include <cuda_runtime.h>
#include <math.h>

#define CH 24          // b*c independent planes
#define HI 192
#define WI 192
#define NI 186         // interior rows/cols (192 - 2*3)
#define RINGROWS 64
#define NBLK 6         // CTAs per plane
#define WARPS 8
#define THREADS (WARPS*32)

// padded row lengths (floats) for conflict-free float4 shared reads
#define W1P 52
#define W2P 100
#define W3P 28
#define FP  52
#define H1P 100
#define H2P 28

__device__ float  g_ring[CH * RINGROWS * WI];   // zero-padded delta rows (cols 0..2, 189..191 stay 0)
__device__ int    g_prog[CH * WI];              // per-row completed-column counters
__device__ double g_sumsq;

__device__ __forceinline__ int ldAcqG(const int* p) {
    int v;
    asm volatile("ld.acquire.gpu.global.b32 %0, [%1];" : "=r"(v) : "l"(p) : "memory");
    return v;
}
__device__ __forceinline__ void stRelG(int* p, int v) {
    asm volatile("st.release.gpu.global.b32 [%0], %1;" :: "l"(p), "r"(v) : "memory");
}

__global__ void zero_kernel() {
    int idx = blockIdx.x * blockDim.x + threadIdx.x;
    int stride = gridDim.x * blockDim.x;
    const int n = CH * RINGROWS * WI;
    for (int i = idx; i < n; i += stride) g_ring[i] = 0.0f;
    for (int i = idx; i < CH * WI; i += stride) g_prog[i] = 0;
    if (idx == 0) g_sumsq = 0.0;
}

__global__ __launch_bounds__(THREADS, 1)
void codec_kernel(const float* __restrict__ x,
                  const float* __restrict__ W1, const float* __restrict__ B1,
                  const float* __restrict__ W2, const float* __restrict__ B2,
                  const float* __restrict__ W3, const float* __restrict__ B3,
                  const float* __restrict__ W4, const float* __restrict__ B4)
{
    __shared__ __align__(16) float sW1[96 * W1P];   // W1^T [m][k], m=0..95, k=0..47
    __shared__ __align__(16) float sW2[24 * W2P];   // W2^T [m][k], m=0..23, k=0..95
    __shared__ __align__(16) float sW3[12 * W3P];   // W3^T [m][k], m=0..11, k=0..23
    __shared__ float sW4[16];
    __shared__ float sB1[96], sB2[24], sB3[12], sB4v;
    __shared__ __align__(16) float sFeat[WARPS][FP];
    __shared__ __align__(16) float sH1[WARPS][H1P];
    __shared__ __align__(16) float sH2[WARPS][H2P];

    const int tid = threadIdx.x;

    for (int idx = tid; idx < 48 * 96; idx += THREADS) {
        int k = idx / 96, m = idx % 96;
        sW1[m * W1P + k] = W1[idx];
    }
    for (int idx = tid; idx < 96 * 24; idx += THREADS) {
        int k = idx / 24, m = idx % 24;
        sW2[m * W2P + k] = W2[idx];
    }
    for (int idx = tid; idx < 24 * 12; idx += THREADS) {
        int k = idx / 12, m = idx % 12;
        sW3[m * W3P + k] = W3[idx];
    }
    if (tid < 12) sW4[tid] = W4[tid];
    if (tid < 96) sB1[tid] = B1[tid];
    if (tid < 24) sB2[tid] = B2[tid];
    if (tid < 12) sB3[tid] = B3[tid];
    if (tid == 0) sB4v = B4[0];
    __syncthreads();

    const int ch   = blockIdx.x / NBLK;
    const int blk  = blockIdx.x % NBLK;
    const int w    = tid >> 5;
    const int lane = tid & 31;
    const int startRow = blk + NBLK * w;   // 0..47 — rows i ≡ startRow (mod 48)

    const float* xch    = x + ch * HI * WI;
    float*       ringCh = g_ring + ch * RINGROWS * WI;
    int*         progCh = g_prog + ch * WI;

    float* featw = sFeat[w];
    float* h1w   = sH1[w];
    float* h2w   = sH2[w];

    const int m0 = lane, m1 = lane + 32, m2 = lane + 64;
    const float bb0 = sB1[m0], bb1 = sB1[m1], bb2 = sB1[m2];
    const float b2l = (lane < 24) ? sB2[lane] : 0.0f;
    const float b3l = (lane < 12) ? sB3[lane] : 0.0f;
    const float w4l = (lane < 12) ? sW4[lane] : 0.0f;
    const float b4v = sB4v;

    const int t1 = lane;        // feat index handled by this lane (pass 1)
    const int t2 = lane + 32;   // feat index (pass 2), valid for lane<16

    double sumsq = 0.0;

    for (int i = startRow; i < NI; i += NBLK * WARPS) {
        // per-row tap base pointers
        const float* p1 = nullptr; const float* q1 = nullptr;
        if (t1 < 21)      { int dy = t1 / 7, dx = t1 % 7; p1 = xch + (i + dy) * WI + dx; }
        else if (t1 < 24) { int dx = t1 - 21;             p1 = xch + (i + 3) * WI + dx; }
        else              { int s = t1 - 24; int dy = s / 7, dx = s % 7;
                            q1 = ringCh + ((unsigned)(i - 3 + dy) & (RINGROWS - 1)) * WI + dx; }
        const float* q2 = nullptr; int kind2 = 0;   // 0 none, 2 ring, 3 last3
        if (lane < 16) {
            if (t2 < 45) { int s = t2 - 24; int dy = s / 7, dx = s % 7;
                           q2 = ringCh + ((unsigned)(i - 3 + dy) & (RINGROWS - 1)) * WI + dx; kind2 = 2; }
            else kind2 = 3;
        }

        const int*   progPrev = progCh + (i - 1);
        int*         progMe   = progCh + i;
        float*       ringW    = ringCh + (i & (RINGROWS - 1)) * WI;
        const float* tgtRow   = xch + (i + 3) * WI + 3;

        int   pc = 0;
        float d0 = 0.0f, d1 = 0.0f, d2 = 0.0f;   // deltas j-3, j-2, j-1

        for (int j = 0; j < NI; ++j) {
            // ---- wavefront wait: predecessor row must be >= 4 columns ahead ----
            if (i > 0) {
                int need = j + 4; if (need > NI) need = NI;
                while (pc < need) pc = ldAcqG(progPrev);
            }
            // ---- gather 48 features ----
            float v1 = (t1 < 24) ? __ldg(p1 + j) : __ldcg(q1 + j);
            featw[t1] = v1;
            if (lane < 16) {
                float v2;
                if (kind2 == 2) v2 = __ldcg(q2 + j);
                else            v2 = (lane == 13) ? d0 : (lane == 14) ? d1 : d2;
                featw[t2] = v2;
            }
            __syncwarp();
            // ---- layer 1: 48 -> 96 (lane owns outputs m, m+32, m+64) ----
            float a0 = bb0, a1 = bb1, a2 = bb2;
            {
                const float4* f4 = (const float4*)featw;
                const float4* wa = (const float4*)(sW1 + m0 * W1P);
                const float4* wb = (const float4*)(sW1 + m1 * W1P);
                const float4* wc = (const float4*)(sW1 + m2 * W1P);
                #pragma unroll
                for (int k = 0; k < 12; ++k) {
                    float4 f = f4[k];
                    float4 A = wa[k]; float4 B = wb[k]; float4 C = wc[k];
                    a0 += f.x*A.x + f.y*A.y + f.z*A.z + f.w*A.w;
                    a1 += f.x*B.x + f.y*B.y + f.z*B.z + f.w*B.w;
                    a2 += f.x*C.x + f.y*C.y + f.z*C.z + f.w*C.w;
                }
            }
            h1w[m0] = tanhf(a0); h1w[m1] = tanhf(a1); h1w[m2] = tanhf(a2);
            __syncwarp();
            // ---- layer 2: 96 -> 24 (lanes 0..23) ----
            if (lane < 24) {
                float acc2 = b2l;
                const float4* h4 = (const float4*)h1w;
                const float4* w2 = (const float4*)(sW2 + lane * W2P);
                #pragma unroll
                for (int k = 0; k < 24; ++k) {
                    float4 h = h4[k]; float4 Wv = w2[k];
                    acc2 += h.x*Wv.x + h.y*Wv.y + h.z*Wv.z + h.w*Wv.w;
                }
                h2w[lane] = tanhf(acc2);
            }
            __syncwarp();
            // ---- layer 3: 24 -> 12 (lanes 0..11), then layer 4 dot-12 ----
            float pr = 0.0f;
            if (lane < 12) {
                float acc3 = b3l;
                const float4* h4 = (const float4*)h2w;
                const float4* w3 = (const float4*)(sW3 + lane * W3P);
                #pragma unroll
                for (int k = 0; k < 6; ++k) {
                    float4 h = h4[k]; float4 Wv = w3[k];
                    acc3 += h.x*Wv.x + h.y*Wv.y + h.z*Wv.z + h.w*Wv.w;
                }
                pr = tanhf(acc3) * w4l;
            }
            pr += __shfl_xor_sync(0xffffffffu, pr, 16);
            pr += __shfl_xor_sync(0xffffffffu, pr, 8);
            pr += __shfl_xor_sync(0xffffffffu, pr, 4);
            pr += __shfl_xor_sync(0xffffffffu, pr, 2);
            pr += __shfl_xor_sync(0xffffffffu, pr, 1);
            float out   = tanhf(pr + b4v);
            float tgt   = __ldg(tgtRow + j);
            float delta = tgt - out;
            d0 = d1; d1 = d2; d2 = delta;
            if (lane == 0) {
                ringW[3 + j] = delta;          // plain STG (L2 write-through)
                stRelG(progMe, j + 1);         // release: orders the delta store
                sumsq += (double)delta * (double)delta;
            }
        }
    }
    if (lane == 0) atomicAdd(&g_sumsq, sumsq);
}

__global__ void finish_kernel(float* out) {
    // divisor matches reference: b*c*(h-2)*w = 8*3*190*192
    out[0] = (float)sqrt(g_sumsq / 875520.0);
}

extern "C" void kernel_launch(void* const* d_in, const int* in_sizes, int n_in,
                              void* d_out, int out_size) {
    const float* x  = (const float*)d_in[0];
    const float* W1 = (const float*)d_in[1];
    const float* b1 = (const float*)d_in[2];
    const float* W2 = (const float*)d_in[3];
    const float* b2 = (const float*)d_in[4];
    const float* W3 = (const float*)d_in[5];
    const float* b3 = (const float*)d_in[6];
    const float* W4 = (const float*)d_in[7];
    const float* b4 = (const float*)d_in[8];

    zero_kernel<<<512, 256>>>();
    codec_kernel<<<CH * NBLK, THREADS>>>(x, W1, b1, W2, b2, W3, b3, W4, b4);
    finish_kernel<<<1, 1>>>((float*)d_out);
}

// round 3
// speedup vs baseline: 1.9252x; 1.9252x over previous
#include <cuda_runtime.h>
#include <math.h>

#define CH 24          // b*c independent planes
#define HI 192
#define WI 192
#define NI 186         // interior rows/cols
#define RINGROWS 64
#define NBLK 6         // CTAs per plane
#define WARPS 8
#define THREADS (WARPS*32)

typedef unsigned long long ull;

__device__ float  g_ring[CH * RINGROWS * WI];   // zero-padded delta rows (only w>=5 rows written)
__device__ int    g_prog[CH * WI];              // per-row completed-column counters (w>=5 rows)
__device__ double g_sumsq;

__device__ __forceinline__ int ldAcqG(const int* p) {
    int v;
    asm volatile("ld.acquire.gpu.global.b32 %0, [%1];" : "=r"(v) : "l"(p) : "memory");
    return v;
}
__device__ __forceinline__ void stRelG(int* p, int v) {
    asm volatile("st.release.gpu.global.b32 [%0], %1;" :: "l"(p), "r"(v) : "memory");
}
__device__ __forceinline__ int ldAcqS(unsigned a) {
    int v;
    asm volatile("ld.acquire.cta.shared.b32 %0, [%1];" : "=r"(v) : "r"(a) : "memory");
    return v;
}
__device__ __forceinline__ void stRelS(unsigned a, int v) {
    asm volatile("st.release.cta.shared.b32 [%0], %1;" :: "r"(a), "r"(v) : "memory");
}
__device__ __forceinline__ void fma2(ull& d, ull a, ull b) {
    asm("fma.rn.f32x2 %0, %1, %2, %0;" : "+l"(d) : "l"(a), "l"(b));
}
__device__ __forceinline__ float hsum2(ull v) {
    float lo, hi;
    asm("mov.b64 {%0, %1}, %2;" : "=f"(lo), "=f"(hi) : "l"(v));
    return lo + hi;
}
// tanh(x) = 1 - 2/(e^{2x}+1), via ex2.approx + rcp.approx; abs err ~1e-6
__device__ __forceinline__ float ftanh(float x) {
    float e = __expf(2.0f * x);
    float r;
    asm("rcp.approx.f32 %0, %1;" : "=f"(r) : "f"(e + 1.0f));
    return fmaf(-2.0f, r, 1.0f);
}

__global__ void zero_kernel() {
    int idx = blockIdx.x * blockDim.x + threadIdx.x;
    int stride = gridDim.x * blockDim.x;
    const int n = CH * RINGROWS * WI;
    for (int i = idx; i < n; i += stride) g_ring[i] = 0.0f;
    for (int i = idx; i < CH * WI; i += stride) g_prog[i] = 0;
    if (idx == 0) g_sumsq = 0.0;
}

__global__ __launch_bounds__(THREADS, 1)
void codec_kernel(const float* __restrict__ x,
                  const float* __restrict__ W1, const float* __restrict__ B1,
                  const float* __restrict__ W2, const float* __restrict__ B2,
                  const float* __restrict__ W3, const float* __restrict__ B3,
                  const float* __restrict__ W4, const float* __restrict__ B4)
{
    // k-major interleaved weights: element [k4*M + m] = float4(W[4k4+0..3][m]) as 2 f32x2 pairs
    __shared__ __align__(16) ulonglong2 sW1q[12 * 96];
    __shared__ __align__(16) ulonglong2 sW2q[24 * 24];
    __shared__ __align__(16) ulonglong2 sW3q[6 * 12];
    __shared__ float sB1[96], sB2[24], sB3[12], sW4[12];
    __shared__ float sB4v;
    __shared__ __align__(16) float sFeat[WARPS][48];
    __shared__ __align__(16) float sH1[WARPS][96];
    __shared__ __align__(16) float sH2[WARPS][24];
    __shared__ __align__(16) float sRing[WARPS][WI];   // per-warp current row deltas (padded cols zero)
    __shared__ int sProg[WARPS];

    const int tid = threadIdx.x;

    {   // load weights into interleaved layout
        float* f1 = (float*)sW1q;
        for (int idx = tid; idx < 48 * 96; idx += THREADS) {
            int k = idx / 96, m = idx % 96;
            f1[((k >> 2) * 96 + m) * 4 + (k & 3)] = W1[idx];
        }
        float* f2 = (float*)sW2q;
        for (int idx = tid; idx < 96 * 24; idx += THREADS) {
            int k = idx / 24, m = idx % 24;
            f2[((k >> 2) * 24 + m) * 4 + (k & 3)] = W2[idx];
        }
        float* f3 = (float*)sW3q;
        for (int idx = tid; idx < 24 * 12; idx += THREADS) {
            int k = idx / 12, m = idx % 12;
            f3[((k >> 2) * 12 + m) * 4 + (k & 3)] = W3[idx];
        }
    }
    if (tid < 96) sB1[tid] = B1[tid];
    if (tid < 24) sB2[tid] = B2[tid];
    if (tid < 12) sB3[tid] = B3[tid];
    if (tid < 12) sW4[tid] = W4[tid];
    if (tid == 0) sB4v = B4[0];
    for (int idx = tid; idx < WARPS * WI; idx += THREADS) ((float*)sRing)[idx] = 0.0f;
    if (tid < WARPS) sProg[tid] = 0;
    __syncthreads();

    const int ch   = blockIdx.x / NBLK;
    const int blk  = blockIdx.x % NBLK;
    const int w    = tid >> 5;
    const int lane = tid & 31;

    const float* xch    = x + ch * HI * WI;
    float*       ringCh = g_ring + ch * RINGROWS * WI;
    int*         progCh = g_prog + ch * WI;

    const unsigned sprogAddr = (unsigned)__cvta_generic_to_shared(&sProg[0]);
    const unsigned sprogOwn  = sprogAddr + w * 4;
    const unsigned sprogPrev = sprogAddr + (w - 1) * 4;

    float* featw = sFeat[w];
    float* h1w   = sH1[w];
    float* h2w   = sH2[w];

    const int m0 = lane, m1 = lane + 32, m2 = lane + 64;
    const float bb0 = sB1[m0], bb1 = sB1[m1], bb2 = sB1[m2];
    const float b2l = (lane < 24) ? sB2[lane] : 0.0f;
    const float b3l = (lane < 12) ? sB3[lane] : 0.0f;
    const float w4l = (lane < 12) ? sW4[lane] : 0.0f;
    const float b4v = sB4v;

    // ---- static tap descriptors (independent of row) ----
    // pass1: t1 = lane (features 0..31); pass2 (lane<16): t2 = lane+32 (features 32..47)
    int p1_dy = 0, p1_dx = 0;           // for t1 in 24..31 (ring taps)
    if (lane >= 24) { int s = lane - 24; p1_dy = (s == 7) ? 1 : 0; p1_dx = (s == 7) ? 0 : s; }
    int p2_dy = 0, p2_dx = 0;           // for lane<13 (ring taps 32..44)
    if (lane < 13) { int s = lane + 8; p2_dy = s / 7; p2_dx = s % 7; }

    double sumsq = 0.0;

    for (int i = 8 * blk + w; i < NI; i += NBLK * WARPS) {
        // ---- image tap pointer (t1 < 24) ----
        const float* imgP = nullptr;
        if (lane < 21)      imgP = xch + (i + lane / 7) * WI + (lane % 7);
        else if (lane < 24) imgP = xch + (i + 3) * WI + (lane - 21);

        // ---- ring tap pointers ----
        const float* r1S = nullptr; const float* r1G = nullptr;
        if (lane >= 24) {
            if (p1_dy >= 3 - w) r1S = &sRing[w - 3 + p1_dy][p1_dx];
            else                r1G = ringCh + ((unsigned)(i - 3 + p1_dy) & (RINGROWS - 1)) * WI + p1_dx;
        }
        const float* r2S = nullptr; const float* r2G = nullptr;
        if (lane < 13) {
            if (p2_dy >= 3 - w) r2S = &sRing[w - 3 + p2_dy][p2_dx];
            else                r2G = ringCh + ((unsigned)(i - 3 + p2_dy) & (RINGROWS - 1)) * WI + p2_dx;
        } else if (lane < 16) {
            r2S = &sRing[w][lane - 13];    // own-row last3 deltas, idx j..j+2 = cols j-3..j-1
        }

        // ---- sync sources for this row ----
        const bool hasShared = (w >= 1);
        const int  sNeedBase = (i - 1) * 256;
        int g0c = NI, g1c = NI, g2c = NI;
        const int *g0p = nullptr, *g1p = nullptr, *g2p = nullptr;
        if (w < 3) {
            int r0 = i - 1 - w; if (r0 >= 0) { g0p = progCh + r0; g0c = 0; }
            if (w < 2) { int r1 = i - 2 - w; if (r1 >= 0) { g1p = progCh + r1; g1c = 0; } }
            if (w < 1) { int r2 = i - 3;     if (r2 >= 0) { g2p = progCh + r2; g2c = 0; } }
        }

        int*         progMe = progCh + i;
        float*       ringW  = ringCh + (i & (RINGROWS - 1)) * WI;
        const float* tgtRow = xch + (i + 3) * WI + 3;
        const bool   pubG   = (w >= 5);

        int spc = 0;

        for (int j = 0; j < NI; ++j) {
            // ---- early independent loads (image taps, target) ----
            float vimg = 0.0f;
            if (lane < 24) vimg = __ldg(imgP + j);
            float tgt = 0.0f;
            if (lane == 0) tgt = __ldg(tgtRow + j);

            // ---- wavefront waits: predecessor rows must be >= 4 columns ahead ----
            int need = j + 4; if (need > NI) need = NI;
            if (hasShared) {
                int sneed = sNeedBase + need;
                while (spc < sneed) spc = ldAcqS(sprogPrev);
            }
            while (g0c < need) g0c = ldAcqG(g0p);
            while (g1c < need) g1c = ldAcqG(g1p);
            while (g2c < need) g2c = ldAcqG(g2p);

            // ---- gather 48 features ----
            float v1;
            if (lane < 24)      v1 = vimg;
            else if (r1S)       v1 = r1S[j];
            else                v1 = __ldcg(r1G + j);
            featw[lane] = v1;
            if (lane < 16) {
                float v2;
                if (r2S) v2 = r2S[j];
                else     v2 = __ldcg(r2G + j);
                featw[lane + 32] = v2;
            }
            __syncwarp();

            // ---- layer 1: 48 -> 96 (lane owns outputs m0, m1, m2) ----
            ull a00 = 0, a01 = 0, a10 = 0, a11 = 0, a20 = 0, a21 = 0;
            {
                const ulonglong2* F2 = (const ulonglong2*)featw;
                #pragma unroll
                for (int k4 = 0; k4 < 12; ++k4) {
                    ulonglong2 f  = F2[k4];
                    ulonglong2 wa = sW1q[k4 * 96 + m0];
                    ulonglong2 wb = sW1q[k4 * 96 + m1];
                    ulonglong2 wc = sW1q[k4 * 96 + m2];
                    fma2(a00, f.x, wa.x); fma2(a01, f.y, wa.y);
                    fma2(a10, f.x, wb.x); fma2(a11, f.y, wb.y);
                    fma2(a20, f.x, wc.x); fma2(a21, f.y, wc.y);
                }
            }
            h1w[m0] = ftanh(bb0 + hsum2(a00) + hsum2(a01));
            h1w[m1] = ftanh(bb1 + hsum2(a10) + hsum2(a11));
            h1w[m2] = ftanh(bb2 + hsum2(a20) + hsum2(a21));
            __syncwarp();

            // ---- layer 2: 96 -> 24 (lanes 0..23) ----
            if (lane < 24) {
                ull a0 = 0, a1 = 0, a2 = 0, a3 = 0;
                const ulonglong2* H2v = (const ulonglong2*)h1w;
                #pragma unroll
                for (int k4 = 0; k4 < 24; k4 += 2) {
                    ulonglong2 h  = H2v[k4];
                    ulonglong2 wv = sW2q[k4 * 24 + lane];
                    fma2(a0, h.x, wv.x); fma2(a1, h.y, wv.y);
                    ulonglong2 h2  = H2v[k4 + 1];
                    ulonglong2 wv2 = sW2q[(k4 + 1) * 24 + lane];
                    fma2(a2, h2.x, wv2.x); fma2(a3, h2.y, wv2.y);
                }
                float v = b2l + (hsum2(a0) + hsum2(a1)) + (hsum2(a2) + hsum2(a3));
                h2w[lane] = ftanh(v);
            }
            __syncwarp();

            // ---- layer 3: 24 -> 12 (lanes 0..11) + layer 4 dot-12 ----
            float pr = 0.0f;
            if (lane < 12) {
                ull a0 = 0, a1 = 0;
                const ulonglong2* H3v = (const ulonglong2*)h2w;
                #pragma unroll
                for (int k4 = 0; k4 < 6; ++k4) {
                    ulonglong2 h  = H3v[k4];
                    ulonglong2 wv = sW3q[k4 * 12 + lane];
                    fma2(a0, h.x, wv.x); fma2(a1, h.y, wv.y);
                }
                pr = ftanh(b3l + hsum2(a0) + hsum2(a1)) * w4l;
            }
            pr += __shfl_xor_sync(0xffffffffu, pr, 8);
            pr += __shfl_xor_sync(0xffffffffu, pr, 4);
            pr += __shfl_xor_sync(0xffffffffu, pr, 2);
            pr += __shfl_xor_sync(0xffffffffu, pr, 1);

            if (lane == 0) {
                float out   = ftanh(pr + b4v);
                float delta = tgt - out;
                sumsq += (double)delta * (double)delta;
                sRing[w][3 + j] = delta;                  // own-row ring (shared)
                stRelS(sprogOwn, i * 256 + (j + 1));      // release: orders the STS above
                if (pubG) {
                    ringW[3 + j] = delta;                 // global ring for next-CTA consumers
                    stRelG(progMe, j + 1);
                }
            }
            __syncwarp();
        }
    }
    if (lane == 0) atomicAdd(&g_sumsq, sumsq);
}

__global__ void finish_kernel(float* out) {
    // divisor matches reference: b*c*(h-2)*w = 8*3*190*192
    out[0] = (float)sqrt(g_sumsq / 875520.0);
}

extern "C" void kernel_launch(void* const* d_in, const int* in_sizes, int n_in,
                              void* d_out, int out_size) {
    const float* x  = (const float*)d_in[0];
    const float* W1 = (const float*)d_in[1];
    const float* b1 = (const float*)d_in[2];
    const float* W2 = (const float*)d_in[3];
    const float* b2 = (const float*)d_in[4];
    const float* W3 = (const float*)d_in[5];
    const float* b3 = (const float*)d_in[6];
    const float* W4 = (const float*)d_in[7];
    const float* b4 = (const float*)d_in[8];

    zero_kernel<<<512, 256>>>();
    codec_kernel<<<CH * NBLK, THREADS>>>(x, W1, b1, W2, b2, W3, b3, W4, b4);
    finish_kernel<<<1, 1>>>((float*)d_out);
}

// round 4
// speedup vs baseline: 2.0985x; 1.0900x over previous
#include <cuda_runtime.h>
#include <math.h>

#define CH 24          // b*c independent planes
#define HI 192
#define WI 192
#define NI 186         // interior rows/cols
#define RINGROWS 64
#define NBLK 6         // CTAs per plane
#define WARPS 8
#define THREADS (WARPS*32)

typedef unsigned long long ull;

__device__ float  g_ring[CH * RINGROWS * WI];   // zero-padded delta rows (only w>=5 rows written)
__device__ int    g_prog[CH * WI];              // per-row completed-column counters (w>=5 rows)
__device__ double g_sumsq;

__device__ __forceinline__ int ldAcqG(const int* p) {
    int v;
    asm volatile("ld.acquire.gpu.global.b32 %0, [%1];" : "=r"(v) : "l"(p) : "memory");
    return v;
}
__device__ __forceinline__ void stRelG(int* p, int v) {
    asm volatile("st.release.gpu.global.b32 [%0], %1;" :: "l"(p), "r"(v) : "memory");
}
__device__ __forceinline__ int ldAcqS(unsigned a) {
    int v;
    asm volatile("ld.acquire.cta.shared.b32 %0, [%1];" : "=r"(v) : "r"(a) : "memory");
    return v;
}
__device__ __forceinline__ void stRelS(unsigned a, int v) {
    asm volatile("st.release.cta.shared.b32 [%0], %1;" :: "r"(a), "r"(v) : "memory");
}
__device__ __forceinline__ void fma2(ull& d, ull a, ull b) {
    asm("fma.rn.f32x2 %0, %1, %2, %0;" : "+l"(d) : "l"(a), "l"(b));
}
__device__ __forceinline__ float hsum2(ull v) {
    float lo, hi;
    asm("mov.b64 {%0, %1}, %2;" : "=f"(lo), "=f"(hi) : "l"(v));
    return lo + hi;
}
__device__ __forceinline__ ull packf2(float lo, float hi) {
    ull r;
    asm("mov.b64 %0, {%1, %2};" : "=l"(r) : "f"(lo), "f"(hi));
    return r;
}
// tanh(x) = 1 - 2/(e^{2x}+1), via ex2.approx + rcp.approx; abs err ~1e-6
__device__ __forceinline__ float ftanh(float x) {
    float e = __expf(2.0f * x);
    float r;
    asm("rcp.approx.f32 %0, %1;" : "=f"(r) : "f"(e + 1.0f));
    return fmaf(-2.0f, r, 1.0f);
}

__global__ void zero_kernel() {
    int idx = blockIdx.x * blockDim.x + threadIdx.x;
    int stride = gridDim.x * blockDim.x;
    const int n = CH * RINGROWS * WI;
    for (int i = idx; i < n; i += stride) g_ring[i] = 0.0f;
    for (int i = idx; i < CH * WI; i += stride) g_prog[i] = 0;
    if (idx == 0) g_sumsq = 0.0;
}

__global__ __launch_bounds__(THREADS, 1)
void codec_kernel(const float* __restrict__ x,
                  const float* __restrict__ W1, const float* __restrict__ B1,
                  const float* __restrict__ W2, const float* __restrict__ B2,
                  const float* __restrict__ W3, const float* __restrict__ B3,
                  const float* __restrict__ W4, const float* __restrict__ B4)
{
    // layer2/3 weights: k-major interleaved, element [k4*M + m] = float4(W[4k4+0..3][m])
    __shared__ __align__(16) ulonglong2 sW2q[24 * 24];
    __shared__ __align__(16) ulonglong2 sW3q[6 * 12];
    __shared__ float sB1[96], sB2[24], sB3[12], sW4[12];
    __shared__ float sB4v;
    __shared__ __align__(16) float sFeat[WARPS][48];
    __shared__ __align__(16) float sH1[WARPS][96];
    __shared__ __align__(16) float sH2[WARPS][24];
    __shared__ __align__(16) float sRing[WARPS][WI];   // per-warp current row deltas (padded cols zero)
    __shared__ int sProg[WARPS];

    const int tid = threadIdx.x;

    {
        float* f2 = (float*)sW2q;
        for (int idx = tid; idx < 96 * 24; idx += THREADS) {
            int k = idx / 24, m = idx % 24;
            f2[((k >> 2) * 24 + m) * 4 + (k & 3)] = W2[idx];
        }
        float* f3 = (float*)sW3q;
        for (int idx = tid; idx < 24 * 12; idx += THREADS) {
            int k = idx / 12, m = idx % 12;
            f3[((k >> 2) * 12 + m) * 4 + (k & 3)] = W3[idx];
        }
    }
    if (tid < 96) sB1[tid] = B1[tid];
    if (tid < 24) sB2[tid] = B2[tid];
    if (tid < 12) sB3[tid] = B3[tid];
    if (tid < 12) sW4[tid] = W4[tid];
    if (tid == 0) sB4v = B4[0];
    for (int idx = tid; idx < WARPS * WI; idx += THREADS) ((float*)sRing)[idx] = 0.0f;
    if (tid < WARPS) sProg[tid] = 0;
    __syncthreads();

    const int ch   = blockIdx.x / NBLK;
    const int blk  = blockIdx.x % NBLK;
    const int w    = tid >> 5;
    const int lane = tid & 31;

    const float* xch    = x + ch * HI * WI;
    float*       ringCh = g_ring + ch * RINGROWS * WI;
    int*         progCh = g_prog + ch * WI;

    const unsigned sprogAddr = (unsigned)__cvta_generic_to_shared(&sProg[0]);
    const unsigned sprogOwn  = sprogAddr + w * 4;
    const unsigned sprogPrev = sprogAddr + (w - 1) * 4;

    float* featw = sFeat[w];
    float* h1w   = sH1[w];
    float* h2w   = sH2[w];

    const int m0 = lane, m1 = lane + 32, m2 = lane + 64;
    const float bb0 = sB1[m0], bb1 = sB1[m1], bb2 = sB1[m2];
    const float b2l = (lane < 24) ? sB2[lane] : 0.0f;
    const float b3l = (lane < 12) ? sB3[lane] : 0.0f;
    const float w4l = (lane < 12) ? sW4[lane] : 0.0f;
    const float b4v = sB4v;

    // ---- layer-1 weights in registers: 72 packed f32x2 per lane ----
    // w1r[k4*6 + mi*2 + h] = (W1[4k4+2h][m_mi], W1[4k4+2h+1][m_mi])
    ull w1r[72];
    #pragma unroll
    for (int k4 = 0; k4 < 12; ++k4) {
        #pragma unroll
        for (int mi = 0; mi < 3; ++mi) {
            int m = lane + 32 * mi;
            int k = 4 * k4;
            w1r[k4 * 6 + mi * 2 + 0] = packf2(__ldg(W1 + (k + 0) * 96 + m), __ldg(W1 + (k + 1) * 96 + m));
            w1r[k4 * 6 + mi * 2 + 1] = packf2(__ldg(W1 + (k + 2) * 96 + m), __ldg(W1 + (k + 3) * 96 + m));
        }
    }

    // ---- static tap descriptors ----
    int p1_dy = 0, p1_dx = 0;           // for t1 in 24..31 (ring taps)
    if (lane >= 24) { int s = lane - 24; p1_dy = (s == 7) ? 1 : 0; p1_dx = (s == 7) ? 0 : s; }
    int p2_dy = 0, p2_dx = 0;           // for lane<13 (ring taps 32..44)
    if (lane < 13) { int s = lane + 8; p2_dy = s / 7; p2_dx = s % 7; }

    double sumsq = 0.0;

    for (int i = 8 * blk + w; i < NI; i += NBLK * WARPS) {
        const float* imgP = nullptr;
        if (lane < 21)      imgP = xch + (i + lane / 7) * WI + (lane % 7);
        else if (lane < 24) imgP = xch + (i + 3) * WI + (lane - 21);

        const float* r1S = nullptr; const float* r1G = nullptr;
        if (lane >= 24) {
            if (p1_dy >= 3 - w) r1S = &sRing[w - 3 + p1_dy][p1_dx];
            else                r1G = ringCh + ((unsigned)(i - 3 + p1_dy) & (RINGROWS - 1)) * WI + p1_dx;
        }
        const float* r2S = nullptr; const float* r2G = nullptr;
        if (lane < 13) {
            if (p2_dy >= 3 - w) r2S = &sRing[w - 3 + p2_dy][p2_dx];
            else                r2G = ringCh + ((unsigned)(i - 3 + p2_dy) & (RINGROWS - 1)) * WI + p2_dx;
        } else if (lane < 16) {
            r2S = &sRing[w][lane - 13];    // own-row last3 deltas
        }

        const bool hasShared = (w >= 1);
        const int  sNeedBase = (i - 1) * 256;
        int g0c = NI, g1c = NI, g2c = NI;
        const int *g0p = nullptr, *g1p = nullptr, *g2p = nullptr;
        if (w < 3) {
            int r0 = i - 1 - w; if (r0 >= 0) { g0p = progCh + r0; g0c = 0; }
            if (w < 2) { int r1 = i - 2 - w; if (r1 >= 0) { g1p = progCh + r1; g1c = 0; } }
            if (w < 1) { int r2 = i - 3;     if (r2 >= 0) { g2p = progCh + r2; g2c = 0; } }
        }

        int*         progMe = progCh + i;
        float*       ringW  = ringCh + (i & (RINGROWS - 1)) * WI;
        const float* tgtRow = xch + (i + 3) * WI + 3;
        const bool   pubG   = (w >= 5);

        int spc = 0;

        for (int j = 0; j < NI; ++j) {
            float vimg = 0.0f;
            if (lane < 24) vimg = __ldg(imgP + j);
            float tgt = 0.0f;
            if (lane == 0) tgt = __ldg(tgtRow + j);

            int need = j + 4; if (need > NI) need = NI;
            if (hasShared) {
                int sneed = sNeedBase + need;
                while (spc < sneed) spc = ldAcqS(sprogPrev);
            }
            while (g0c < need) g0c = ldAcqG(g0p);
            while (g1c < need) g1c = ldAcqG(g1p);
            while (g2c < need) g2c = ldAcqG(g2p);

            float v1;
            if (lane < 24)      v1 = vimg;
            else if (r1S)       v1 = r1S[j];
            else                v1 = __ldcg(r1G + j);
            featw[lane] = v1;
            if (lane < 16) {
                float v2;
                if (r2S) v2 = r2S[j];
                else     v2 = __ldcg(r2G + j);
                featw[lane + 32] = v2;
            }
            __syncwarp();

            // ---- layer 1: 48 -> 96, weights in registers ----
            ull a00 = 0, a01 = 0, a10 = 0, a11 = 0, a20 = 0, a21 = 0;
            {
                const ulonglong2* F2 = (const ulonglong2*)featw;
                #pragma unroll
                for (int k4 = 0; k4 < 12; ++k4) {
                    ulonglong2 f = F2[k4];
                    fma2(a00, f.x, w1r[k4 * 6 + 0]); fma2(a01, f.y, w1r[k4 * 6 + 1]);
                    fma2(a10, f.x, w1r[k4 * 6 + 2]); fma2(a11, f.y, w1r[k4 * 6 + 3]);
                    fma2(a20, f.x, w1r[k4 * 6 + 4]); fma2(a21, f.y, w1r[k4 * 6 + 5]);
                }
            }
            h1w[m0] = ftanh(bb0 + hsum2(a00) + hsum2(a01));
            h1w[m1] = ftanh(bb1 + hsum2(a10) + hsum2(a11));
            h1w[m2] = ftanh(bb2 + hsum2(a20) + hsum2(a21));
            __syncwarp();

            // ---- layer 2: 96 -> 24 (lanes 0..23) ----
            if (lane < 24) {
                ull a0 = 0, a1 = 0, a2 = 0, a3 = 0;
                const ulonglong2* H2v = (const ulonglong2*)h1w;
                #pragma unroll
                for (int k4 = 0; k4 < 24; k4 += 2) {
                    ulonglong2 h  = H2v[k4];
                    ulonglong2 wv = sW2q[k4 * 24 + lane];
                    fma2(a0, h.x, wv.x); fma2(a1, h.y, wv.y);
                    ulonglong2 h2  = H2v[k4 + 1];
                    ulonglong2 wv2 = sW2q[(k4 + 1) * 24 + lane];
                    fma2(a2, h2.x, wv2.x); fma2(a3, h2.y, wv2.y);
                }
                float v = b2l + (hsum2(a0) + hsum2(a1)) + (hsum2(a2) + hsum2(a3));
                h2w[lane] = ftanh(v);
            }
            __syncwarp();

            // ---- layer 3: 24 -> 12 (lanes 0..11) + layer 4 dot-12 ----
            float pr = 0.0f;
            if (lane < 12) {
                ull a0 = 0, a1 = 0;
                const ulonglong2* H3v = (const ulonglong2*)h2w;
                #pragma unroll
                for (int k4 = 0; k4 < 6; ++k4) {
                    ulonglong2 h  = H3v[k4];
                    ulonglong2 wv = sW3q[k4 * 12 + lane];
                    fma2(a0, h.x, wv.x); fma2(a1, h.y, wv.y);
                }
                pr = ftanh(b3l + hsum2(a0) + hsum2(a1)) * w4l;
            }
            pr += __shfl_xor_sync(0xffffffffu, pr, 8);
            pr += __shfl_xor_sync(0xffffffffu, pr, 4);
            pr += __shfl_xor_sync(0xffffffffu, pr, 2);
            pr += __shfl_xor_sync(0xffffffffu, pr, 1);

            if (lane == 0) {
                float out   = ftanh(pr + b4v);
                float delta = tgt - out;
                sumsq += (double)delta * (double)delta;
                sRing[w][3 + j] = delta;                  // own-row ring (shared)
                stRelS(sprogOwn, i * 256 + (j + 1));      // release: orders the STS above
                if (pubG) {
                    ringW[3 + j] = delta;                 // global ring for next-CTA consumers
                    stRelG(progMe, j + 1);
                }
            }
            __syncwarp();
        }
    }
    if (lane == 0) atomicAdd(&g_sumsq, sumsq);
}

__global__ void finish_kernel(float* out) {
    // divisor matches reference: b*c*(h-2)*w = 8*3*190*192
    out[0] = (float)sqrt(g_sumsq / 875520.0);
}

extern "C" void kernel_launch(void* const* d_in, const int* in_sizes, int n_in,
                              void* d_out, int out_size) {
    const float* x  = (const float*)d_in[0];
    const float* W1 = (const float*)d_in[1];
    const float* b1 = (const float*)d_in[2];
    const float* W2 = (const float*)d_in[3];
    const float* b2 = (const float*)d_in[4];
    const float* W3 = (const float*)d_in[5];
    const float* b3 = (const float*)d_in[6];
    const float* W4 = (const float*)d_in[7];
    const float* b4 = (const float*)d_in[8];

    zero_kernel<<<512, 256>>>();
    codec_kernel<<<CH * NBLK, THREADS>>>(x, W1, b1, W2, b2, W3, b3, W4, b4);
    finish_kernel<<<1, 1>>>((float*)d_out);
}